// round 2
// baseline (speedup 1.0000x reference)
#include <cuda_runtime.h>
#include <math.h>

#define C_    6
#define A_    1024
#define HW_   16384
#define NROWS 65536
#define NPIX  65536

// ---------------- device scratch (no allocations allowed) ----------------
__device__ float g_sums[C_ * A_];
__device__ float g_cnt[C_];
__device__ float g_protoN[C_ * A_];
__device__ float g_Mc[C_];
__device__ float g_Sc[C_];
__device__ float g_L1;
__device__ float g_L2;

// ---------------- f32x2 packed helpers (sm_100+) ----------------
__device__ __forceinline__ unsigned long long pk(float lo, float hi) {
    unsigned long long r;
    asm("mov.b64 %0, {%1, %2};" : "=l"(r) : "f"(lo), "f"(hi));
    return r;
}
__device__ __forceinline__ void upk(unsigned long long v, float& lo, float& hi) {
    asm("mov.b64 {%0, %1}, %2;" : "=f"(lo), "=f"(hi) : "l"(v));
}
__device__ __forceinline__ unsigned long long fma2(unsigned long long a,
                                                   unsigned long long b,
                                                   unsigned long long c) {
    unsigned long long d;
    asm("fma.rn.f32x2 %0, %1, %2, %3;" : "=l"(d) : "l"(a), "l"(b), "l"(c));
    return d;
}

// ---------------- kernel 0: zero accumulators ----------------
__global__ void zero_kernel() {
    int i = blockIdx.x * blockDim.x + threadIdx.x;
    if (i < C_ * A_) g_sums[i] = 0.f;
    if (i < C_) g_cnt[i] = 0.f;
    if (i == 0) { g_L1 = 0.f; g_L2 = 0.f; }
}

// ---------------- kernel 1: per-class segment sums of srcfeat ----------------
__device__ __forceinline__ void seg_accum(int c, const float4& v,
                                          float4 acc[6], float cnt[6], bool leader) {
    if ((unsigned)c >= 6u) return;  // includes IGNORE_LABEL=255
    switch (c) {
#define SEG_CASE(i) \
        case i: acc[i].x += v.x; acc[i].y += v.y; acc[i].z += v.z; acc[i].w += v.w; \
                if (leader) cnt[i] += 1.0f; break;
        SEG_CASE(0) SEG_CASE(1) SEG_CASE(2) SEG_CASE(3) SEG_CASE(4) SEG_CASE(5)
#undef SEG_CASE
    }
}

__global__ void __launch_bounds__(256) seg_kernel(const float* __restrict__ src,
                                                  const int* __restrict__ labels) {
    const int col = threadIdx.x << 2;          // 4 columns per thread -> 1024 per block
    const bool leader = (threadIdx.x == 0);
    float4 acc[6];
#pragma unroll
    for (int c = 0; c < 6; c++) acc[c] = make_float4(0.f, 0.f, 0.f, 0.f);
    float cnt[6] = {0.f, 0.f, 0.f, 0.f, 0.f, 0.f};

    const int stride = gridDim.x;
    int r = blockIdx.x;
    // unroll 2 rows for MLP
    for (; r + stride < NROWS; r += 2 * stride) {
        int l0 = labels[r];
        int l1 = labels[r + stride];
        float4 v0 = *reinterpret_cast<const float4*>(src + (size_t)r * A_ + col);
        float4 v1 = *reinterpret_cast<const float4*>(src + (size_t)(r + stride) * A_ + col);
        seg_accum(l0, v0, acc, cnt, leader);
        seg_accum(l1, v1, acc, cnt, leader);
    }
    if (r < NROWS) {
        int l0 = labels[r];
        float4 v0 = *reinterpret_cast<const float4*>(src + (size_t)r * A_ + col);
        seg_accum(l0, v0, acc, cnt, leader);
    }

#pragma unroll
    for (int c = 0; c < 6; c++) {
        atomicAdd(&g_sums[c * A_ + col + 0], acc[c].x);
        atomicAdd(&g_sums[c * A_ + col + 1], acc[c].y);
        atomicAdd(&g_sums[c * A_ + col + 2], acc[c].z);
        atomicAdd(&g_sums[c * A_ + col + 3], acc[c].w);
    }
    if (leader) {
#pragma unroll
        for (int c = 0; c < 6; c++) atomicAdd(&g_cnt[c], cnt[c]);
    }
}

// ---------------- kernel 2: normalize prototypes ----------------
__global__ void protonorm_kernel(const float* __restrict__ Proto) {
    const int c = threadIdx.x >> 5;
    const int lane = threadIdx.x & 31;
    if (c >= 6) return;
    float ss = 0.f;
    for (int a = lane; a < A_; a += 32) {
        float v = Proto[c * A_ + a];
        ss = fmaf(v, v, ss);
    }
#pragma unroll
    for (int o = 16; o > 0; o >>= 1) ss += __shfl_xor_sync(0xffffffffu, ss, o);
    float inv = 1.0f / fmaxf(sqrtf(ss), 1e-12f);
    for (int a = lane; a < A_; a += 32)
        g_protoN[c * A_ + a] = Proto[c * A_ + a] * inv;
}

// ---------------- kernel 3: per-class softmax stats over tarout pixels ----------------
__global__ void __launch_bounds__(1024) stats_kernel(const float* __restrict__ tarout) {
    const int c = blockIdx.x;
    const int tid = threadIdx.x;
    __shared__ float red[1024];

    float m = -3.4e38f;
    for (int p = tid; p < NPIX; p += 1024) {
        int b = p >> 14;
        int q = p & (HW_ - 1);
        float t = tarout[(size_t)b * (C_ * HW_) + (size_t)c * HW_ + q];
        m = fmaxf(m, t);
    }
    red[tid] = m;
    __syncthreads();
    for (int s = 512; s > 0; s >>= 1) {
        if (tid < s) red[tid] = fmaxf(red[tid], red[tid + s]);
        __syncthreads();
    }
    const float M = red[0];
    __syncthreads();

    float acc = 0.f;
    for (int p = tid; p < NPIX; p += 1024) {
        int b = p >> 14;
        int q = p & (HW_ - 1);
        float t = tarout[(size_t)b * (C_ * HW_) + (size_t)c * HW_ + q];
        acc += expf(t - M);
    }
    red[tid] = acc;
    __syncthreads();
    for (int s = 512; s > 0; s >>= 1) {
        if (tid < s) red[tid] += red[tid + s];
        __syncthreads();
    }
    if (tid == 0) { g_Mc[c] = M; g_Sc[c] = red[0]; }
}

// ---------------- kernel 4: contrast + both loss accumulations ----------------
// 512 blocks x 128 threads. Block = one tile of 128 consecutive pixels inside one image.
// Warp w handles channels [w*256, (w+1)*256); lane handles 4 consecutive pixels (float4).
__global__ void __launch_bounds__(128) contrast_kernel(const float* __restrict__ tarfeat,
                                                       const float* __restrict__ tarout) {
    __shared__ float sProto[C_ * A_];   // 24 KB
    __shared__ float sP[7][4][128];     // 14 KB: 6 dots + ss, per warp, per pixel
    __shared__ float sRed[8];

    const int tid = threadIdx.x;
    const int wid = tid >> 5;
    const int lane = tid & 31;

    for (int i = tid; i < C_ * A_; i += 128) sProto[i] = g_protoN[i];
    __syncthreads();

    const int T = blockIdx.x;
    const int b = T >> 7;                 // 128 tiles per image
    const int pixBase = (T & 127) << 7;   // 128 pixels per tile
    const float* base = tarfeat + (size_t)b * ((size_t)A_ * HW_) + pixBase + (lane << 2);

    unsigned long long dxy[6], dzw[6], ssxy = 0ull, sszw = 0ull;
#pragma unroll
    for (int c = 0; c < 6; c++) { dxy[c] = 0ull; dzw[c] = 0ull; }

    const int a0 = wid << 8;
#pragma unroll 1
    for (int a = a0; a < a0 + 256; a += 4) {
        float4 v[4];
#pragma unroll
        for (int j = 0; j < 4; j++)
            v[j] = *reinterpret_cast<const float4*>(base + (size_t)(a + j) * HW_);
#pragma unroll
        for (int j = 0; j < 4; j++) {
            unsigned long long vxy = pk(v[j].x, v[j].y);
            unsigned long long vzw = pk(v[j].z, v[j].w);
            ssxy = fma2(vxy, vxy, ssxy);
            sszw = fma2(vzw, vzw, sszw);
#pragma unroll
            for (int c = 0; c < 6; c++) {
                float pn = sProto[c * A_ + a + j];
                unsigned long long pp = pk(pn, pn);
                dxy[c] = fma2(vxy, pp, dxy[c]);
                dzw[c] = fma2(vzw, pp, dzw[c]);
            }
        }
    }

    // dump per-warp partials: pixel slot = 4*lane + s
#pragma unroll
    for (int c = 0; c < 6; c++) {
        float x0, x1, x2, x3;
        upk(dxy[c], x0, x1);
        upk(dzw[c], x2, x3);
        sP[c][wid][lane * 4 + 0] = x0;
        sP[c][wid][lane * 4 + 1] = x1;
        sP[c][wid][lane * 4 + 2] = x2;
        sP[c][wid][lane * 4 + 3] = x3;
    }
    {
        float x0, x1, x2, x3;
        upk(ssxy, x0, x1);
        upk(sszw, x2, x3);
        sP[6][wid][lane * 4 + 0] = x0;
        sP[6][wid][lane * 4 + 1] = x1;
        sP[6][wid][lane * 4 + 2] = x2;
        sP[6][wid][lane * 4 + 3] = x3;
    }
    __syncthreads();

    // epilogue: thread tid owns pixel (pixBase + tid)
    float d[6], ss;
#pragma unroll
    for (int c = 0; c < 6; c++)
        d[c] = sP[c][0][tid] + sP[c][1][tid] + sP[c][2][tid] + sP[c][3][tid];
    ss = sP[6][0][tid] + sP[6][1][tid] + sP[6][2][tid] + sP[6][3][tid];

    const float inv = 1.0f / fmaxf(sqrtf(ss), 1e-12f);
    const int pix = pixBase + tid;
    const float* to = tarout + (size_t)b * ((size_t)C_ * HW_) + pix;

    float t[6];
#pragma unroll
    for (int c = 0; c < 6; c++) t[c] = to[(size_t)c * HW_];
    float tm = t[0];
#pragma unroll
    for (int c = 1; c < 6; c++) tm = fmaxf(tm, t[c]);
    float e1[6], s1 = 0.f;
#pragma unroll
    for (int c = 0; c < 6; c++) { e1[c] = expf(t[c] - tm); s1 += e1[c]; }

    float L1p = 0.f, L2p = 0.f;
#pragma unroll
    for (int c = 0; c < 6; c++) {
        float con = d[c] * inv;
        L1p = fmaf(e1[c], con, L1p);
        L2p = fmaf(expf(t[c] - g_Mc[c]) * (1.0f / g_Sc[c]), con, L2p);
    }
    L1p /= s1;

#pragma unroll
    for (int o = 16; o > 0; o >>= 1) {
        L1p += __shfl_xor_sync(0xffffffffu, L1p, o);
        L2p += __shfl_xor_sync(0xffffffffu, L2p, o);
    }
    if (lane == 0) { sRed[wid] = L1p; sRed[4 + wid] = L2p; }
    __syncthreads();
    if (tid == 0) {
        atomicAdd(&g_L1, sRed[0] + sRed[1] + sRed[2] + sRed[3]);
        atomicAdd(&g_L2, sRed[4] + sRed[5] + sRed[6] + sRed[7]);
    }
}

// ---------------- kernel 5: finalize mean into output ----------------
__global__ void mean_kernel(float* __restrict__ out, int out_size) {
    int i = blockIdx.x * blockDim.x + threadIdx.x;
    if (i < C_ * A_ && (i + 1) < out_size)
        out[1 + i] = g_sums[i] / fmaxf(g_cnt[i >> 10], 1.0f);
}

// ---------------- kernel 6: finalize loss ----------------
__global__ void fin_kernel(float* __restrict__ out, int out_size) {
    if (threadIdx.x == 0 && out_size >= 1) {
        float loss1 = 1.0f - g_L1 * (1.0f / (float)NPIX);
        float loss2 = 1.0f - g_L2 * (1.0f / (float)C_);
        out[0] = loss1 + loss2;
    }
}

// ---------------- launch ----------------
extern "C" void kernel_launch(void* const* d_in, const int* in_sizes, int n_in,
                              void* d_out, int out_size) {
    const float* Proto   = (const float*)d_in[0];
    const float* srcfeat = (const float*)d_in[1];
    const float* tarfeat = (const float*)d_in[2];
    const float* tarout  = (const float*)d_in[3];
    const int* labels    = (const int*)d_in[4];   // JAX w/o x64: int64 request -> int32 buffer
    float* out = (float*)d_out;

    zero_kernel<<<24, 256>>>();
    seg_kernel<<<296, 256>>>(srcfeat, labels);
    protonorm_kernel<<<1, 192>>>(Proto);
    stats_kernel<<<6, 1024>>>(tarout);
    contrast_kernel<<<512, 128>>>(tarfeat, tarout);
    mean_kernel<<<24, 256>>>(out, out_size);
    fin_kernel<<<1, 32>>>(out, out_size);
}

// round 3
// speedup vs baseline: 1.4039x; 1.4039x over previous
#include <cuda_runtime.h>
#include <math.h>

#define C_    6
#define A_    1024
#define HW_   16384
#define NROWS 65536
#define NPIX  65536

// ---------------- device scratch ----------------
__device__ float g_sums[C_ * A_];
__device__ float g_cnt[C_];
__device__ float g_protoN[C_ * A_];
__device__ float g_Sc[C_];          // per-class sum of exp(tarout) over all pixels
__device__ float g_L1;
__device__ float g_L2;

// ---------------- f32x2 packed helpers (sm_100+) ----------------
__device__ __forceinline__ unsigned long long pk(float lo, float hi) {
    unsigned long long r;
    asm("mov.b64 %0, {%1, %2};" : "=l"(r) : "f"(lo), "f"(hi));
    return r;
}
__device__ __forceinline__ void upk(unsigned long long v, float& lo, float& hi) {
    asm("mov.b64 {%0, %1}, %2;" : "=f"(lo), "=f"(hi) : "l"(v));
}
__device__ __forceinline__ unsigned long long fma2(unsigned long long a,
                                                   unsigned long long b,
                                                   unsigned long long c) {
    unsigned long long d;
    asm("fma.rn.f32x2 %0, %1, %2, %3;" : "=l"(d) : "l"(a), "l"(b), "l"(c));
    return d;
}

// ---------------- kernel 0: zero accumulators ----------------
__global__ void zero_kernel() {
    int i = blockIdx.x * blockDim.x + threadIdx.x;
    if (i < C_ * A_) g_sums[i] = 0.f;
    if (i < C_) { g_cnt[i] = 0.f; g_Sc[i] = 0.f; }
    if (i == 0) { g_L1 = 0.f; g_L2 = 0.f; }
}

// ---------------- kernel 1: per-class segment sums of srcfeat ----------------
__device__ __forceinline__ void seg_accum(int c, const float4& v,
                                          float4 acc[6], float cnt[6], bool leader) {
    if ((unsigned)c >= 6u) return;  // includes IGNORE_LABEL=255
    switch (c) {
#define SEG_CASE(i) \
        case i: acc[i].x += v.x; acc[i].y += v.y; acc[i].z += v.z; acc[i].w += v.w; \
                if (leader) cnt[i] += 1.0f; break;
        SEG_CASE(0) SEG_CASE(1) SEG_CASE(2) SEG_CASE(3) SEG_CASE(4) SEG_CASE(5)
#undef SEG_CASE
    }
}

__global__ void __launch_bounds__(256) seg_kernel(const float* __restrict__ src,
                                                  const int* __restrict__ labels) {
    const int col = threadIdx.x << 2;
    const bool leader = (threadIdx.x == 0);
    float4 acc[6];
#pragma unroll
    for (int c = 0; c < 6; c++) acc[c] = make_float4(0.f, 0.f, 0.f, 0.f);
    float cnt[6] = {0.f, 0.f, 0.f, 0.f, 0.f, 0.f};

    const int stride = gridDim.x;
    int r = blockIdx.x;
    // 4 rows in flight for MLP
    for (; r + 3 * stride < NROWS; r += 4 * stride) {
        int l0 = labels[r];
        int l1 = labels[r + stride];
        int l2 = labels[r + 2 * stride];
        int l3 = labels[r + 3 * stride];
        float4 v0 = __ldcs(reinterpret_cast<const float4*>(src + (size_t)r * A_ + col));
        float4 v1 = __ldcs(reinterpret_cast<const float4*>(src + (size_t)(r + stride) * A_ + col));
        float4 v2 = __ldcs(reinterpret_cast<const float4*>(src + (size_t)(r + 2 * stride) * A_ + col));
        float4 v3 = __ldcs(reinterpret_cast<const float4*>(src + (size_t)(r + 3 * stride) * A_ + col));
        seg_accum(l0, v0, acc, cnt, leader);
        seg_accum(l1, v1, acc, cnt, leader);
        seg_accum(l2, v2, acc, cnt, leader);
        seg_accum(l3, v3, acc, cnt, leader);
    }
    for (; r < NROWS; r += stride) {
        int l0 = labels[r];
        float4 v0 = __ldcs(reinterpret_cast<const float4*>(src + (size_t)r * A_ + col));
        seg_accum(l0, v0, acc, cnt, leader);
    }

#pragma unroll
    for (int c = 0; c < 6; c++) {
        atomicAdd(&g_sums[c * A_ + col + 0], acc[c].x);
        atomicAdd(&g_sums[c * A_ + col + 1], acc[c].y);
        atomicAdd(&g_sums[c * A_ + col + 2], acc[c].z);
        atomicAdd(&g_sums[c * A_ + col + 3], acc[c].w);
    }
    if (leader) {
#pragma unroll
        for (int c = 0; c < 6; c++) atomicAdd(&g_cnt[c], cnt[c]);
    }
}

// ---------------- kernel 2: fused proto-normalize + per-class exp-sum stats ----
// blocks 0..5   : normalize prototype row (blockIdx.x)
// blocks 6..101 : stats over a 4096-element contiguous chunk of tarout
__global__ void __launch_bounds__(256) protostats_kernel(const float* __restrict__ Proto,
                                                         const float* __restrict__ tarout) {
    __shared__ float red[256];
    const int tid = threadIdx.x;

    if (blockIdx.x < 6) {
        const int c = blockIdx.x;
        float4 v = *reinterpret_cast<const float4*>(Proto + c * A_ + (tid << 2));
        float ss = v.x * v.x + v.y * v.y + v.z * v.z + v.w * v.w;
        red[tid] = ss;
        __syncthreads();
        for (int s = 128; s > 0; s >>= 1) {
            if (tid < s) red[tid] += red[tid + s];
            __syncthreads();
        }
        const float inv = 1.0f / fmaxf(sqrtf(red[0]), 1e-12f);
        float4 o = make_float4(v.x * inv, v.y * inv, v.z * inv, v.w * inv);
        *reinterpret_cast<float4*>(g_protoN + c * A_ + (tid << 2)) = o;
    } else {
        const int sIdx = blockIdx.x - 6;            // 0..95
        const int base = sIdx << 12;                // 4096 elements per block
        const int c = (sIdx >> 2) % 6;              // class of this chunk
        float acc = 0.f;
#pragma unroll
        for (int k = 0; k < 4; k++) {
            float4 t = __ldcs(reinterpret_cast<const float4*>(tarout + base + k * 1024 + (tid << 2)));
            acc += __expf(t.x) + __expf(t.y) + __expf(t.z) + __expf(t.w);
        }
        red[tid] = acc;
        __syncthreads();
        for (int s = 128; s > 0; s >>= 1) {
            if (tid < s) red[tid] += red[tid + s];
            __syncthreads();
        }
        if (tid == 0) atomicAdd(&g_Sc[c], red[0]);
    }
}

// ---------------- kernel 3: contrast + both loss accumulations ----------------
// 1024 blocks x 128 threads. Block = 64 consecutive pixels of one image.
// Warp w covers channels [w*256, (w+1)*256); lane owns 2 pixels (float2).
__global__ void __launch_bounds__(128) contrast_kernel(const float* __restrict__ tarfeat,
                                                       const float* __restrict__ tarout) {
    __shared__ float sProto[C_ * A_];   // 24 KB
    __shared__ float sP[7][4][64];      // 7 KB: 6 dots + ss, per warp, per pixel
    __shared__ float sRed[4];

    const int tid = threadIdx.x;
    const int wid = tid >> 5;
    const int lane = tid & 31;

    for (int i = tid; i < C_ * A_ / 4; i += 128)
        reinterpret_cast<float4*>(sProto)[i] = reinterpret_cast<const float4*>(g_protoN)[i];
    __syncthreads();

    const int T = blockIdx.x;
    const int b = T >> 8;                 // 256 tiles per image
    const int pixBase = (T & 255) << 6;   // 64 pixels per tile
    const float* base = tarfeat + (size_t)b * ((size_t)A_ * HW_) + pixBase + (lane << 1);

    unsigned long long d2[6], ss2 = 0ull;
#pragma unroll
    for (int c = 0; c < 6; c++) d2[c] = 0ull;

    const int a0 = wid << 8;
#pragma unroll 1
    for (int a = a0; a < a0 + 256; a += 8) {
        float2 v[8];
#pragma unroll
        for (int j = 0; j < 8; j++)
            v[j] = __ldcs(reinterpret_cast<const float2*>(base + (size_t)(a + j) * HW_));
#pragma unroll
        for (int j = 0; j < 8; j++) {
            unsigned long long vv = pk(v[j].x, v[j].y);
            ss2 = fma2(vv, vv, ss2);
#pragma unroll
            for (int c = 0; c < 6; c++) {
                float pn = sProto[c * A_ + a + j];
                d2[c] = fma2(vv, pk(pn, pn), d2[c]);
            }
        }
    }

    // per-warp partials: pixel slot = 2*lane + {0,1}
#pragma unroll
    for (int c = 0; c < 6; c++) {
        float x0, x1;
        upk(d2[c], x0, x1);
        sP[c][wid][lane * 2 + 0] = x0;
        sP[c][wid][lane * 2 + 1] = x1;
    }
    {
        float x0, x1;
        upk(ss2, x0, x1);
        sP[6][wid][lane * 2 + 0] = x0;
        sP[6][wid][lane * 2 + 1] = x1;
    }
    __syncthreads();

    float L1p = 0.f, L2p = 0.f;
    if (tid < 64) {
        float d[6], ss;
#pragma unroll
        for (int c = 0; c < 6; c++)
            d[c] = sP[c][0][tid] + sP[c][1][tid] + sP[c][2][tid] + sP[c][3][tid];
        ss = sP[6][0][tid] + sP[6][1][tid] + sP[6][2][tid] + sP[6][3][tid];

        const float inv = rsqrtf(fmaxf(ss, 1e-24f));
        const int pix = pixBase + tid;
        const float* to = tarout + (size_t)b * ((size_t)C_ * HW_) + pix;

        float e1[6], s1 = 0.f;
#pragma unroll
        for (int c = 0; c < 6; c++) {
            e1[c] = __expf(to[(size_t)c * HW_]);
            s1 += e1[c];
        }
#pragma unroll
        for (int c = 0; c < 6; c++) {
            float con = d[c] * inv;
            L1p = fmaf(e1[c], con, L1p);
            L2p = fmaf(e1[c] * (1.0f / g_Sc[c]), con, L2p);
        }
        L1p /= s1;
    }

#pragma unroll
    for (int o = 16; o > 0; o >>= 1) {
        L1p += __shfl_xor_sync(0xffffffffu, L1p, o);
        L2p += __shfl_xor_sync(0xffffffffu, L2p, o);
    }
    if (lane == 0 && wid < 2) { sRed[wid] = L1p; sRed[2 + wid] = L2p; }
    __syncthreads();
    if (tid == 0) {
        atomicAdd(&g_L1, sRed[0] + sRed[1]);
        atomicAdd(&g_L2, sRed[2] + sRed[3]);
    }
}

// ---------------- kernel 4: finalize mean + loss ----------------
__global__ void meanfin_kernel(float* __restrict__ out, int out_size) {
    int i = blockIdx.x * blockDim.x + threadIdx.x;
    if (i < C_ * A_ && (i + 1) < out_size)
        out[1 + i] = g_sums[i] / fmaxf(g_cnt[i >> 10], 1.0f);
    if (i == 0 && out_size >= 1) {
        float loss1 = 1.0f - g_L1 * (1.0f / (float)NPIX);
        float loss2 = 1.0f - g_L2 * (1.0f / (float)C_);
        out[0] = loss1 + loss2;
    }
}

// ---------------- launch ----------------
extern "C" void kernel_launch(void* const* d_in, const int* in_sizes, int n_in,
                              void* d_out, int out_size) {
    const float* Proto   = (const float*)d_in[0];
    const float* srcfeat = (const float*)d_in[1];
    const float* tarfeat = (const float*)d_in[2];
    const float* tarout  = (const float*)d_in[3];
    const int* labels    = (const int*)d_in[4];
    float* out = (float*)d_out;

    zero_kernel<<<24, 256>>>();
    seg_kernel<<<296, 256>>>(srcfeat, labels);
    protostats_kernel<<<102, 256>>>(Proto, tarout);
    contrast_kernel<<<1024, 128>>>(tarfeat, tarout);
    meanfin_kernel<<<24, 256>>>(out, out_size);
}